// round 16
// baseline (speedup 1.0000x reference)
#include <cuda_runtime.h>
#include <cuda_bf16.h>
#include <cstdint>
#include <cstddef>

// ---------------------------------------------------------------------------
// FocusedLinearAttention — round 16:
//   kv2_mma -> 1 CTA per head (grid 40): no atomics, no zero_kernel,
//   direct ksum store; frees 108 SMs so conv_s (side stream) truly overlaps.
// ---------------------------------------------------------------------------

#define BATCH 8
#define SEQ   4096
#define CH    640
#define CC    (CH*CH)
#define NH    5
#define HD    128
#define BH    (BATCH*NH)   // 40

#define BMM 128
#define BNN 128
#define BKE 32
#define NCHB (CH/BKE)           // 20
#define RWB 80
#define BUFB (128*RWB)
#define OFFAH 0
#define OFFAL BUFB
#define OFFBH (2*BUFB)
#define OFFBL (3*BUFB)
#define STB   (4*BUFB)          // 40960 B
#define SMEM_GB (2*STB)         // 81920 B -> 2 CTAs/SM

#define T2RW 272
#define T2BUF (32*T2RW)
#define OKH 0
#define OKL T2BUF
#define OVH (2*T2BUF)
#define OVL (3*T2BUF)
#define T2ST (4*T2BUF)          // 34816
#define SMEM_KV2 (2*T2ST)       // 69632

__device__ float g_q[BATCH*SEQ*CH];
__device__ float g_k[BATCH*SEQ*CH];
__device__ float g_x[BATCH*SEQ*CH];
__device__ __nv_bfloat16 g_abh[BATCH*SEQ*CH];
__device__ __nv_bfloat16 g_abl[BATCH*SEQ*CH];
__device__ __nv_bfloat16 g_a2h[BATCH*SEQ*CH];
__device__ __nv_bfloat16 g_a2l[BATCH*SEQ*CH];
__device__ __nv_bfloat16 g_qbh[BATCH*SEQ*CH];
__device__ __nv_bfloat16 g_qbl[BATCH*SEQ*CH];
__device__ __nv_bfloat16 g_kbh[BATCH*SEQ*CH];
__device__ __nv_bfloat16 g_kbl[BATCH*SEQ*CH];
__device__ __nv_bfloat16 g_vbh[BATCH*SEQ*CH];
__device__ __nv_bfloat16 g_vbl[BATCH*SEQ*CH];
__device__ __nv_bfloat16 g_wbh[4*CC];
__device__ __nv_bfloat16 g_wbl[4*CC];
__device__ __nv_bfloat16 g_k2h[BH*HD*HD];
__device__ __nv_bfloat16 g_k2l[BH*HD*HD];
__device__ float g_kv2[BH*HD*HD];
__device__ float g_ksum[BH*HD];
__device__ float g_sc[CH];

// ---------------------------------------------------------------------------
__device__ __forceinline__ void cp16(uint32_t dst, const void* src) {
    asm volatile("cp.async.cg.shared.global [%0], [%1], 16;" :: "r"(dst), "l"(src));
}

#define LDM4(r0, r1, r2, r3, a) \
    asm volatile("ldmatrix.sync.aligned.m8n8.x4.shared.b16 {%0,%1,%2,%3}, [%4];" \
        : "=r"(r0), "=r"(r1), "=r"(r2), "=r"(r3) : "r"(a))

#define LDM4T(r0, r1, r2, r3, a) \
    asm volatile("ldmatrix.sync.aligned.m8n8.x4.trans.shared.b16 {%0,%1,%2,%3}, [%4];" \
        : "=r"(r0), "=r"(r1), "=r"(r2), "=r"(r3) : "r"(a))

#define MMA_BF16(d, a, b) \
    asm volatile( \
        "mma.sync.aligned.m16n8k16.row.col.f32.bf16.bf16.f32 " \
        "{%0,%1,%2,%3}, {%4,%5,%6,%7}, {%8,%9}, {%0,%1,%2,%3};" \
        : "+f"((d)[0]), "+f"((d)[1]), "+f"((d)[2]), "+f"((d)[3]) \
        : "r"((a)[0]), "r"((a)[1]), "r"((a)[2]), "r"((a)[3]), \
          "r"((b)[0]), "r"((b)[1]))

// ---------------------------------------------------------------------------
__device__ __forceinline__ void split4(float4 v, __nv_bfloat16* hp, __nv_bfloat16* lp) {
    float f[4] = { v.x, v.y, v.z, v.w };
    __nv_bfloat16 h[4], l[4];
#pragma unroll
    for (int j = 0; j < 4; j++) {
        h[j] = __float2bfloat16_rn(f[j]);
        l[j] = __float2bfloat16_rn(f[j] - __bfloat162float(h[j]));
    }
    *reinterpret_cast<__nv_bfloat162*>(hp)     = { h[0], h[1] };
    *reinterpret_cast<__nv_bfloat162*>(hp + 2) = { h[2], h[3] };
    *reinterpret_cast<__nv_bfloat162*>(lp)     = { l[0], l[1] };
    *reinterpret_cast<__nv_bfloat162*>(lp + 2) = { l[2], l[3] };
}

// merged x1+x2 split
__global__ __launch_bounds__(256) void split_x12(
    const float* __restrict__ x1, const float* __restrict__ x2, int n4)
{
    int nb = gridDim.x >> 1;
    const float* src; __nv_bfloat16 *hi, *lo;
    int bi = blockIdx.x;
    if (bi < nb) { src = x1; hi = g_abh; lo = g_abl; }
    else         { src = x2; hi = g_a2h; lo = g_a2l; bi -= nb; }
    int i = bi * 256 + threadIdx.x;
    if (i >= n4) return;
    split4(reinterpret_cast<const float4*>(src)[i], hi + 4 * i, lo + 4 * i);
}

__global__ __launch_bounds__(256) void split_w(
    const float* __restrict__ Wq, const float* __restrict__ Wkv,
    const float* __restrict__ Wproj)
{
    int i = blockIdx.x * 256 + threadIdx.x;
    int fi = i * 4;
    const float* src; int off;
    if (fi < CC)          { src = Wq;    off = 0; }
    else if (fi < 3 * CC) { src = Wkv;   off = CC; }
    else                  { src = Wproj; off = 3 * CC; }
    float4 v = *reinterpret_cast<const float4*>(&src[fi - off]);
    split4(v, g_wbh + fi, g_wbl + fi);
}

// ---------------------------------------------------------------------------
// common bf16x3 GEMM core (K = 640); single-sync pipelined mainloop
// ---------------------------------------------------------------------------
__device__ __forceinline__ void gemm_core(
    const __nv_bfloat16* __restrict__ Ah, const __nv_bfloat16* __restrict__ Al,
    const __nv_bfloat16* __restrict__ Bh, const __nv_bfloat16* __restrict__ Bl,
    float* __restrict__ Cout, const float* __restrict__ bias,
    __nv_bfloat16* __restrict__ Hsp, __nv_bfloat16* __restrict__ Lsp,
    int m0, int nb0, int n0, uint32_t sb)
{
    const int tid = threadIdx.x;
    const int lane = tid & 31;
    const int wid = tid >> 5;
    const int warp_m = wid >> 1;
    const int warp_n = wid & 1;
    const int gid = lane >> 2;
    const int tig = lane & 3;
    const int lr = (lane & 7) + ((lane >> 3) & 1) * 8;
    const uint32_t lc = (uint32_t)(((lane >> 4) & 1) * 16);

    float acc[2][8][4];
#pragma unroll
    for (int t = 0; t < 2; t++)
#pragma unroll
        for (int j = 0; j < 8; j++)
#pragma unroll
            for (int e = 0; e < 4; e++) acc[t][j][e] = 0.f;

    int r0f = tid >> 2, c0f = tid & 3;
    int r1f = (tid + 256) >> 2, c1f = (tid + 256) & 3;
    const uint32_t so0 = (uint32_t)(r0f * RWB + c0f * 16);
    const uint32_t so1 = (uint32_t)(r1f * RWB + c1f * 16);
    const size_t gA0 = (size_t)(m0 + r0f) * CH + c0f * 8;
    const size_t gA1 = (size_t)(m0 + r1f) * CH + c1f * 8;
    const size_t gB0 = (size_t)(nb0 + r0f) * CH + c0f * 8;
    const size_t gB1 = (size_t)(nb0 + r1f) * CH + c1f * 8;

    auto fill = [&](int stage, int chunk) {
        const int k0 = chunk * BKE;
        const uint32_t stb = sb + (uint32_t)(stage * STB);
        cp16(stb + OFFAH + so0, Ah + gA0 + k0);
        cp16(stb + OFFAL + so0, Al + gA0 + k0);
        cp16(stb + OFFBH + so0, Bh + gB0 + k0);
        cp16(stb + OFFBL + so0, Bl + gB0 + k0);
        cp16(stb + OFFAH + so1, Ah + gA1 + k0);
        cp16(stb + OFFAL + so1, Al + gA1 + k0);
        cp16(stb + OFFBH + so1, Bh + gB1 + k0);
        cp16(stb + OFFBL + so1, Bl + gB1 + k0);
        asm volatile("cp.async.commit_group;" ::: "memory");
    };

    const uint32_t raF = (uint32_t)((warp_m * 32 + lr) * RWB) + lc;
    const uint32_t rbF = (uint32_t)((warp_n * 64 + lr) * RWB) + lc;

    fill(0, 0);
    for (int i = 0; i < NCHB; i++) {
        asm volatile("cp.async.wait_group 0;" ::: "memory");
        __syncthreads();
        if (i + 1 < NCHB) fill((i + 1) & 1, i + 1);

        const uint32_t stb = sb + (uint32_t)((i & 1) * STB);
#pragma unroll
        for (int ks = 0; ks < 2; ks++) {
            const uint32_t kofs = (uint32_t)(ks * 32);
            uint32_t ah[2][4], al[2][4];
#pragma unroll
            for (int t = 0; t < 2; t++) {
                uint32_t ra = stb + OFFAH + raF + (uint32_t)(t * 16 * RWB) + kofs;
                LDM4(ah[t][0], ah[t][1], ah[t][2], ah[t][3], ra);
                LDM4(al[t][0], al[t][1], al[t][2], al[t][3], ra + (OFFAL - OFFAH));
            }
#pragma unroll
            for (int g = 0; g < 4; g++) {
                uint32_t rb = stb + OFFBH + rbF + (uint32_t)(g * 16 * RWB) + kofs;
                uint32_t bh4[4], bl4[4];
                LDM4(bh4[0], bh4[1], bh4[2], bh4[3], rb);
                uint32_t b0h[2] = { bh4[0], bh4[2] }, b1h[2] = { bh4[1], bh4[3] };
#pragma unroll
                for (int t = 0; t < 2; t++) {
                    MMA_BF16(acc[t][2*g],   ah[t], b0h);
                    MMA_BF16(acc[t][2*g+1], ah[t], b1h);
                }
                LDM4(bl4[0], bl4[1], bl4[2], bl4[3], rb + (OFFBL - OFFBH));
                uint32_t b0l[2] = { bl4[0], bl4[2] }, b1l[2] = { bl4[1], bl4[3] };
#pragma unroll
                for (int t = 0; t < 2; t++) {
                    MMA_BF16(acc[t][2*g],   al[t], b0h);
                    MMA_BF16(acc[t][2*g+1], al[t], b1h);
                }
#pragma unroll
                for (int t = 0; t < 2; t++) {
                    MMA_BF16(acc[t][2*g],   ah[t], b0l);
                    MMA_BF16(acc[t][2*g+1], ah[t], b1l);
                }
            }
        }
    }

#pragma unroll
    for (int t = 0; t < 2; t++) {
        int r0 = m0 + warp_m * 32 + t * 16 + gid;
#pragma unroll
        for (int j = 0; j < 8; j++) {
            int cc = n0 + warp_n * 64 + j * 8 + 2 * tig;
            float b0 = bias ? bias[cc] : 0.f;
            float b1 = bias ? bias[cc + 1] : 0.f;
            float f00 = acc[t][j][0] + b0, f01 = acc[t][j][1] + b1;
            float f10 = acc[t][j][2] + b0, f11 = acc[t][j][3] + b1;
            if (Cout) {
                *reinterpret_cast<float2*>(&Cout[(size_t)r0 * CH + cc]) =
                    make_float2(f00, f01);
                *reinterpret_cast<float2*>(&Cout[(size_t)(r0 + 8) * CH + cc]) =
                    make_float2(f10, f11);
            }
            if (Hsp) {
                __nv_bfloat16 h0 = __float2bfloat16_rn(f00);
                __nv_bfloat16 h1 = __float2bfloat16_rn(f01);
                __nv_bfloat16 h2 = __float2bfloat16_rn(f10);
                __nv_bfloat16 h3 = __float2bfloat16_rn(f11);
                __nv_bfloat16 l0 = __float2bfloat16_rn(f00 - __bfloat162float(h0));
                __nv_bfloat16 l1 = __float2bfloat16_rn(f01 - __bfloat162float(h1));
                __nv_bfloat16 l2 = __float2bfloat16_rn(f10 - __bfloat162float(h2));
                __nv_bfloat16 l3 = __float2bfloat16_rn(f11 - __bfloat162float(h3));
                *reinterpret_cast<__nv_bfloat162*>(&Hsp[(size_t)r0 * CH + cc]) = { h0, h1 };
                *reinterpret_cast<__nv_bfloat162*>(&Hsp[(size_t)(r0 + 8) * CH + cc]) = { h2, h3 };
                *reinterpret_cast<__nv_bfloat162*>(&Lsp[(size_t)r0 * CH + cc]) = { l0, l1 };
                *reinterpret_cast<__nv_bfloat162*>(&Lsp[(size_t)(r0 + 8) * CH + cc]) = { l2, l3 };
            }
        }
    }
}

// merged v + kq GEMM: grid (15, 256); v -> split-only output
__global__ __launch_bounds__(256, 2) void gemm_merged() {
    extern __shared__ char smem[];
    const uint32_t sb = (uint32_t)__cvta_generic_to_shared(smem);
    const int m0 = blockIdx.y * BMM;
    const int bx = blockIdx.x;
    if (bx < 5) {
        gemm_core(g_a2h, g_a2l, g_wbh, g_wbl, nullptr, nullptr,
                  g_vbh, g_vbl, m0, bx * BNN, bx * BNN, sb);
    } else {
        int nb0 = (bx - 5) * BNN;
        if (nb0 < CH)
            gemm_core(g_abh, g_abl, g_wbh + CC, g_wbl + CC, g_k, nullptr,
                      nullptr, nullptr, m0, nb0, nb0, sb);
        else
            gemm_core(g_abh, g_abl, g_wbh + CC, g_wbl + CC, g_q, nullptr,
                      nullptr, nullptr, m0, nb0, nb0 - CH, sb);
    }
}

// proj GEMM: grid (5, 256)
__global__ __launch_bounds__(256, 2) void gemm_proj(
    float* __restrict__ out, const float* __restrict__ bias)
{
    extern __shared__ char smem[];
    const uint32_t sb = (uint32_t)__cvta_generic_to_shared(smem);
    gemm_core(g_abh, g_abl, g_wbh + 3 * CC, g_wbl + 3 * CC, out, bias,
              nullptr, nullptr,
              blockIdx.y * BMM, blockIdx.x * BNN, blockIdx.x * BNN, sb);
}

// ---------------------------------------------------------------------------
// kv2: ONE CTA per head (grid BH). 128 j-iterations, no atomics.
// Direct stores of kv2 [c][d] fp32 and ksum.
// ---------------------------------------------------------------------------
__global__ __launch_bounds__(256, 2) void kv2_mma() {
    extern __shared__ char smem[];
    const uint32_t sb = (uint32_t)__cvta_generic_to_shared(smem);
    const int bh = blockIdx.x;
    const int b = bh / NH, hoff = (bh % NH) * HD;
    const __nv_bfloat16* Kh = g_kbh + (size_t)b * SEQ * CH + hoff;
    const __nv_bfloat16* Kl = g_kbl + (size_t)b * SEQ * CH + hoff;
    const __nv_bfloat16* Vh = g_vbh + (size_t)b * SEQ * CH + hoff;
    const __nv_bfloat16* Vl = g_vbl + (size_t)b * SEQ * CH + hoff;

    const int tid = threadIdx.x;
    const int lane = tid & 31;
    const int wid = tid >> 5;
    const int warp_m = wid >> 1;
    const int warp_n = wid & 1;
    const int gid = lane >> 2;
    const int tig = lane & 3;
    const int grp = lane >> 3;
    const int l8 = lane & 7;

    float acc[2][8][4];
#pragma unroll
    for (int t = 0; t < 2; t++)
#pragma unroll
        for (int j = 0; j < 8; j++)
#pragma unroll
            for (int e = 0; e < 4; e++) acc[t][j][e] = 0.f;

    float kacc = 0.f;

    auto fill = [&](int stage, int it) {
        const int j0 = it * 32;
        const uint32_t stb = sb + (uint32_t)(stage * T2ST);
#pragma unroll
        for (int t = 0; t < 2; t++) {
            int u = tid + t * 256;
            int row = u >> 4, col = u & 15;
            uint32_t off = (uint32_t)(row * T2RW + col * 16);
            size_t g = (size_t)(j0 + row) * CH + col * 8;
            cp16(stb + OKH + off, Kh + g);
            cp16(stb + OKL + off, Kl + g);
            cp16(stb + OVH + off, Vh + g);
            cp16(stb + OVL + off, Vl + g);
        }
        asm volatile("cp.async.commit_group;" ::: "memory");
    };

    fill(0, 0);
    for (int it = 0; it < 128; it++) {
        asm volatile("cp.async.wait_group 0;" ::: "memory");
        __syncthreads();
        if (it + 1 < 128) fill((it + 1) & 1, it + 1);

        const uint32_t stb = sb + (uint32_t)((it & 1) * T2ST);

        if (tid < 128) {
            const __nv_bfloat16* KhS = reinterpret_cast<const __nv_bfloat16*>(
                smem + (it & 1) * T2ST + OKH);
            const __nv_bfloat16* KlS = reinterpret_cast<const __nv_bfloat16*>(
                smem + (it & 1) * T2ST + OKL);
#pragma unroll
            for (int j = 0; j < 32; j++)
                kacc += __bfloat162float(KhS[j * (T2RW / 2) + tid]) +
                        __bfloat162float(KlS[j * (T2RW / 2) + tid]);
        }

#pragma unroll
        for (int ks = 0; ks < 2; ks++) {
            const uint32_t aj = (uint32_t)(ks * 16 + ((grp >> 1) & 1) * 8 + l8);
            uint32_t ah[2][4], al[2][4];
#pragma unroll
            for (int t = 0; t < 2; t++) {
                uint32_t ac = (uint32_t)(warp_m * 32 + t * 16 + (grp & 1) * 8);
                uint32_t ra = stb + OKH + aj * T2RW + ac * 2;
                LDM4T(ah[t][0], ah[t][1], ah[t][2], ah[t][3], ra);
                LDM4T(al[t][0], al[t][1], al[t][2], al[t][3], ra + (OKL - OKH));
            }
            const uint32_t bj = (uint32_t)(ks * 16 + (grp & 1) * 8 + l8);
#pragma unroll
            for (int g = 0; g < 4; g++) {
                uint32_t bd = (uint32_t)(warp_n * 64 + g * 16 + ((grp >> 1) & 1) * 8);
                uint32_t rb = stb + OVH + bj * T2RW + bd * 2;
                uint32_t bh4[4], bl4[4];
                LDM4T(bh4[0], bh4[1], bh4[2], bh4[3], rb);
                uint32_t b0h[2] = { bh4[0], bh4[1] }, b1h[2] = { bh4[2], bh4[3] };
#pragma unroll
                for (int t = 0; t < 2; t++) {
                    MMA_BF16(acc[t][2*g],   ah[t], b0h);
                    MMA_BF16(acc[t][2*g+1], ah[t], b1h);
                }
                LDM4T(bl4[0], bl4[1], bl4[2], bl4[3], rb + (OVL - OVH));
                uint32_t b0l[2] = { bl4[0], bl4[1] }, b1l[2] = { bl4[2], bl4[3] };
#pragma unroll
                for (int t = 0; t < 2; t++) {
                    MMA_BF16(acc[t][2*g],   al[t], b0h);
                    MMA_BF16(acc[t][2*g+1], al[t], b1h);
                }
#pragma unroll
                for (int t = 0; t < 2; t++) {
                    MMA_BF16(acc[t][2*g],   ah[t], b0l);
                    MMA_BF16(acc[t][2*g+1], ah[t], b1l);
                }
            }
        }
    }

    if (tid < 128) g_ksum[bh * HD + tid] = kacc;

    float* dst = g_kv2 + bh * HD * HD;
#pragma unroll
    for (int t = 0; t < 2; t++) {
        int c0 = warp_m * 32 + t * 16 + gid;
#pragma unroll
        for (int j = 0; j < 8; j++) {
            int d = warp_n * 64 + j * 8 + 2 * tig;
            *reinterpret_cast<float2*>(&dst[c0 * HD + d]) =
                make_float2(acc[t][j][0], acc[t][j][1]);
            *reinterpret_cast<float2*>(&dst[(c0 + 8) * HD + d]) =
                make_float2(acc[t][j][2], acc[t][j][3]);
        }
    }
}

// ---------------------------------------------------------------------------
// attn GEMM with fused z (K=128, 4 chunks); single-sync loop
// ---------------------------------------------------------------------------
__global__ __launch_bounds__(256, 2) void attn_gemm() {
    extern __shared__ char smem[];
    const uint32_t sb = (uint32_t)__cvta_generic_to_shared(smem);
    const int bx = blockIdx.x;
    const int bh = bx >> 5;
    const int m0 = (bx & 31) * BMM;
    const int b = bh / NH, hoff = (bh % NH) * HD;
    const __nv_bfloat16* Ah = g_qbh + (size_t)b * SEQ * CH + hoff;
    const __nv_bfloat16* Al = g_qbl + (size_t)b * SEQ * CH + hoff;
    const __nv_bfloat16* Bh = g_k2h + (size_t)bh * HD * HD;
    const __nv_bfloat16* Bl = g_k2l + (size_t)bh * HD * HD;

    const int tid = threadIdx.x;
    const int lane = tid & 31;
    const int wid = tid >> 5;
    const int warp_m = wid >> 1;
    const int warp_n = wid & 1;
    const int gid = lane >> 2;
    const int tig = lane & 3;
    const int lr = (lane & 7) + ((lane >> 3) & 1) * 8;
    const uint32_t lc = (uint32_t)(((lane >> 4) & 1) * 16);

    float acc[2][8][4];
#pragma unroll
    for (int t = 0; t < 2; t++)
#pragma unroll
        for (int j = 0; j < 8; j++)
#pragma unroll
            for (int e = 0; e < 4; e++) acc[t][j][e] = 0.f;

    int r0f = tid >> 2, c0f = tid & 3;
    int r1f = (tid + 256) >> 2, c1f = (tid + 256) & 3;
    const uint32_t so0 = (uint32_t)(r0f * RWB + c0f * 16);
    const uint32_t so1 = (uint32_t)(r1f * RWB + c1f * 16);
    const size_t gA0 = (size_t)(m0 + r0f) * CH + c0f * 8;
    const size_t gA1 = (size_t)(m0 + r1f) * CH + c1f * 8;
    const size_t gB0 = (size_t)r0f * HD + c0f * 8;
    const size_t gB1 = (size_t)r1f * HD + c1f * 8;

    auto fill = [&](int stage, int chunk) {
        const int k0 = chunk * BKE;
        const uint32_t stb = sb + (uint32_t)(stage * STB);
        cp16(stb + OFFAH + so0, Ah + gA0 + k0);
        cp16(stb + OFFAL + so0, Al + gA0 + k0);
        cp16(stb + OFFBH + so0, Bh + gB0 + k0);
        cp16(stb + OFFBL + so0, Bl + gB0 + k0);
        cp16(stb + OFFAH + so1, Ah + gA1 + k0);
        cp16(stb + OFFAL + so1, Al + gA1 + k0);
        cp16(stb + OFFBH + so1, Bh + gB1 + k0);
        cp16(stb + OFFBL + so1, Bl + gB1 + k0);
        asm volatile("cp.async.commit_group;" ::: "memory");
    };

    const uint32_t raF = (uint32_t)((warp_m * 32 + lr) * RWB) + lc;
    const uint32_t rbF = (uint32_t)((warp_n * 64 + lr) * RWB) + lc;

    float zacc = 0.f;

    fill(0, 0);
#pragma unroll
    for (int i = 0; i < 4; i++) {
        asm volatile("cp.async.wait_group 0;" ::: "memory");
        __syncthreads();
        if (i + 1 < 4) fill((i + 1) & 1, i + 1);

        const uint32_t stb = sb + (uint32_t)((i & 1) * STB);

        if (tid < 128) {
            const uint32_t qh = stb + OFFAH + (uint32_t)(tid * RWB);
            const float* ksp = g_ksum + bh * HD + i * BKE;
#pragma unroll
            for (int cc = 0; cc < 32; cc += 2) {
                uint32_t hv, lv;
                asm("ld.shared.b32 %0, [%1];" : "=r"(hv) : "r"(qh + cc * 2));
                asm("ld.shared.b32 %0, [%1];" : "=r"(lv)
                    : "r"(qh + (OFFAL - OFFAH) + cc * 2));
                __nv_bfloat162 h2 = *reinterpret_cast<__nv_bfloat162*>(&hv);
                __nv_bfloat162 l2 = *reinterpret_cast<__nv_bfloat162*>(&lv);
                float q0 = __bfloat162float(h2.x) + __bfloat162float(l2.x);
                float q1 = __bfloat162float(h2.y) + __bfloat162float(l2.y);
                zacc += q0 * __ldg(ksp + cc) + q1 * __ldg(ksp + cc + 1);
            }
        }

#pragma unroll
        for (int ks = 0; ks < 2; ks++) {
            const uint32_t kofs = (uint32_t)(ks * 32);
            uint32_t ah[2][4], al[2][4];
#pragma unroll
            for (int t = 0; t < 2; t++) {
                uint32_t ra = stb + OFFAH + raF + (uint32_t)(t * 16 * RWB) + kofs;
                LDM4(ah[t][0], ah[t][1], ah[t][2], ah[t][3], ra);
                LDM4(al[t][0], al[t][1], al[t][2], al[t][3], ra + (OFFAL - OFFAH));
            }
#pragma unroll
            for (int g = 0; g < 4; g++) {
                uint32_t rb = stb + OFFBH + rbF + (uint32_t)(g * 16 * RWB) + kofs;
                uint32_t bh4[4], bl4[4];
                LDM4(bh4[0], bh4[1], bh4[2], bh4[3], rb);
                uint32_t b0h[2] = { bh4[0], bh4[2] }, b1h[2] = { bh4[1], bh4[3] };
#pragma unroll
                for (int t = 0; t < 2; t++) {
                    MMA_BF16(acc[t][2*g],   ah[t], b0h);
                    MMA_BF16(acc[t][2*g+1], ah[t], b1h);
                }
                LDM4(bl4[0], bl4[1], bl4[2], bl4[3], rb + (OFFBL - OFFBH));
                uint32_t b0l[2] = { bl4[0], bl4[2] }, b1l[2] = { bl4[1], bl4[3] };
#pragma unroll
                for (int t = 0; t < 2; t++) {
                    MMA_BF16(acc[t][2*g],   al[t], b0h);
                    MMA_BF16(acc[t][2*g+1], al[t], b1h);
                }
#pragma unroll
                for (int t = 0; t < 2; t++) {
                    MMA_BF16(acc[t][2*g],   ah[t], b0l);
                    MMA_BF16(acc[t][2*g+1], ah[t], b1l);
                }
            }
        }
    }

    __syncthreads();
    float* zs = reinterpret_cast<float*>(smem);
    if (tid < 128) zs[tid] = 1.f / (zacc + 1e-6f);
    __syncthreads();

#pragma unroll
    for (int t = 0; t < 2; t++) {
        int lr0 = warp_m * 32 + t * 16 + gid;
#pragma unroll
        for (int j = 0; j < 8; j++) {
            int d = warp_n * 64 + j * 8 + 2 * tig;
#pragma unroll
            for (int half = 0; half < 2; half++) {
                int lrow = lr0 + half * 8;
                int i = m0 + lrow;
                float zv = zs[lrow];
                size_t base = (size_t)(b * SEQ + i) * CH + hoff + d;
                float f0 = g_x[base]     + acc[t][j][half * 2]     * zv;
                float f1 = g_x[base + 1] + acc[t][j][half * 2 + 1] * zv;
                __nv_bfloat16 h0 = __float2bfloat16_rn(f0);
                __nv_bfloat16 h1 = __float2bfloat16_rn(f1);
                __nv_bfloat16 l0 = __float2bfloat16_rn(f0 - __bfloat162float(h0));
                __nv_bfloat16 l1 = __float2bfloat16_rn(f1 - __bfloat162float(h1));
                *reinterpret_cast<__nv_bfloat162*>(&g_abh[base]) = { h0, h1 };
                *reinterpret_cast<__nv_bfloat162*>(&g_abl[base]) = { l0, l1 };
            }
        }
    }
}

// ---------------------------------------------------------------------------
__global__ void softplus_kernel(const float* __restrict__ scale) {
    int c = blockIdx.x * 256 + threadIdx.x;
    if (c < CH) g_sc[c] = log1pf(expf(scale[c]));
}

// ---------------------------------------------------------------------------
__device__ __forceinline__ float warp_sum(float s) {
#pragma unroll
    for (int o = 16; o > 0; o >>= 1) s += __shfl_xor_sync(0xffffffffu, s, o);
    return s;
}

// qknorm: warp per row; q and k both -> bf16 hi/lo.
__global__ __launch_bounds__(256) void qknorm_kernel(const float* __restrict__ pos) {
    const int w = blockIdx.x * 8 + (threadIdx.x >> 5);
    const int lane = threadIdx.x & 31;
    const size_t row = (size_t)w;
    const int n = w & (SEQ - 1);
    const float* qrow = g_q + row * CH;
    const float* krow = g_k + row * CH;
    const float* prow = pos + (size_t)n * CH;

    float scv[20];
#pragma unroll
    for (int t = 0; t < 20; t++) scv[t] = g_sc[lane + 32 * t];

    {
        float v[20]; float s = 0.f;
#pragma unroll
        for (int t = 0; t < 20; t++) {
            float raw = qrow[lane + 32 * t];
            float val = (fmaxf(raw, 0.f) + 1e-6f) / scv[t];
            v[t] = val; s += val * val;
        }
        float n1 = sqrtf(warp_sum(s));
        s = 0.f;
#pragma unroll
        for (int t = 0; t < 20; t++) { float c3 = v[t]*v[t]*v[t]; v[t] = c3; s += c3*c3; }
        float sc2 = n1 / sqrtf(warp_sum(s));
#pragma unroll
        for (int t = 0; t < 20; t++) {
            float f = v[t] * sc2;
            __nv_bfloat16 h = __float2bfloat16_rn(f);
            __nv_bfloat16 l = __float2bfloat16_rn(f - __bfloat162float(h));
            g_qbh[row * CH + lane + 32 * t] = h;
            g_qbl[row * CH + lane + 32 * t] = l;
        }
    }
    {
        float v[20]; float s = 0.f;
#pragma unroll
        for (int t = 0; t < 20; t++) {
            float raw = krow[lane + 32 * t] + prow[lane + 32 * t];
            float val = (fmaxf(raw, 0.f) + 1e-6f) / scv[t];
            v[t] = val; s += val * val;
        }
        float n1 = sqrtf(warp_sum(s));
        s = 0.f;
#pragma unroll
        for (int t = 0; t < 20; t++) { float c3 = v[t]*v[t]*v[t]; v[t] = c3; s += c3*c3; }
        float sc2 = n1 / sqrtf(warp_sum(s));
#pragma unroll
        for (int t = 0; t < 20; t++) {
            float f = v[t] * sc2;
            __nv_bfloat16 h = __float2bfloat16_rn(f);
            __nv_bfloat16 l = __float2bfloat16_rn(f - __bfloat162float(h));
            g_kbh[row * CH + lane + 32 * t] = h;
            g_kbl[row * CH + lane + 32 * t] = l;
        }
    }
}

// kv2^T + bf16 split: [bh][c][d] fp32 -> [bh][d][c] hi/lo
__global__ __launch_bounds__(256) void kv2t_split() {
    const int bh = blockIdx.x;
    const int e = blockIdx.y * 256 + threadIdx.x;
    const int d = e >> 7, c = e & 127;
    float v = g_kv2[bh * HD * HD + c * HD + d];
    __nv_bfloat16 h = __float2bfloat16_rn(v);
    __nv_bfloat16 l = __float2bfloat16_rn(v - __bfloat162float(h));
    g_k2h[bh * HD * HD + d * HD + c] = h;
    g_k2l[bh * HD * HD + d * HD + c] = l;
}

// ---------------------------------------------------------------------------
// depthwise conv reading v hi/lo splits
// ---------------------------------------------------------------------------
__global__ __launch_bounds__(256) void conv_s(
    const float* __restrict__ w, const float* __restrict__ bias)
{
    extern __shared__ float sv[];   // [8][68][32]
    const int bh = blockIdx.x, yt = blockIdx.y, dc = blockIdx.z;
    const int b = bh / NH, hoff = (bh % NH) * HD;
    const int tid = threadIdx.x;
    const int d = tid & 31;
    const int xg = tid >> 5;
    const __nv_bfloat16* vh = g_vbh + (size_t)b * SEQ * CH + hoff + dc * 32;
    const __nv_bfloat16* vl = g_vbl + (size_t)b * SEQ * CH + hoff + dc * 32;

    {
        int p = tid;
        int r = p >> 5, rest = p & 31;
        int xi = rest >> 3, d4 = rest & 7;
        int ix = (xi < 2) ? xi : (xi + 64);
        *reinterpret_cast<float4*>(&sv[(r * 68 + ix) * 32 + d4 * 4]) =
            make_float4(0.f, 0.f, 0.f, 0.f);
    }
    for (int p = tid; p < 2048; p += 256) {
        int r = p >> 8, rest = p & 255;
        int x = rest >> 2, d8 = rest & 3;
        int y = yt * 4 - 2 + r;
        float f[8];
        if ((unsigned)y < 64u) {
            uint4 hv = *reinterpret_cast<const uint4*>(
                &vh[(size_t)(y * 64 + x) * CH + d8 * 8]);
            uint4 lv = *reinterpret_cast<const uint4*>(
                &vl[(size_t)(y * 64 + x) * CH + d8 * 8]);
            const __nv_bfloat162* h2 = reinterpret_cast<const __nv_bfloat162*>(&hv);
            const __nv_bfloat162* l2 = reinterpret_cast<const __nv_bfloat162*>(&lv);
#pragma unroll
            for (int j = 0; j < 4; j++) {
                f[2*j]   = __bfloat162float(h2[j].x) + __bfloat162float(l2[j].x);
                f[2*j+1] = __bfloat162float(h2[j].y) + __bfloat162float(l2[j].y);
            }
        } else {
#pragma unroll
            for (int j = 0; j < 8; j++) f[j] = 0.f;
        }
        float* dst = &sv[(r * 68 + x + 2) * 32 + d8 * 8];
        *reinterpret_cast<float4*>(dst)     = make_float4(f[0], f[1], f[2], f[3]);
        *reinterpret_cast<float4*>(dst + 4) = make_float4(f[4], f[5], f[6], f[7]);
    }
    __syncthreads();

    float wr[25];
#pragma unroll
    for (int k = 0; k < 25; k++) wr[k] = __ldg(&w[(dc * 32 + d) * 25 + k]);
    const float bv = __ldg(&bias[dc * 32 + d]);

#pragma unroll
    for (int y = 0; y < 4; y++) {
#pragma unroll
        for (int xo = 0; xo < 8; xo++) {
            int x = xg * 8 + xo;
            float acc = bv;
#pragma unroll
            for (int ky = 0; ky < 5; ky++)
#pragma unroll
                for (int kx = 0; kx < 5; kx++)
                    acc += wr[ky * 5 + kx] * sv[((y + ky) * 68 + (x + kx)) * 32 + d];
            int oy = yt * 4 + y;
            g_x[(size_t)(b * SEQ + oy * 64 + x) * CH + hoff + dc * 32 + d] = acc;
        }
    }
}

// ---------------------------------------------------------------------------
extern "C" void kernel_launch(void* const* d_in, const int* in_sizes, int n_in,
                              void* d_out, int out_size)
{
    const float* x1    = (const float*)d_in[0];
    const float* x2    = (const float*)d_in[1];
    const float* Wq    = (const float*)d_in[2];
    const float* Wkv   = (const float*)d_in[3];
    const float* Wproj = (const float*)d_in[4];
    const float* bproj = (const float*)d_in[5];
    const float* dwc_w = (const float*)d_in[6];
    const float* dwc_b = (const float*)d_in[7];
    const float* scale = (const float*)d_in[8];
    const float* pos   = (const float*)d_in[9];
    float* out = (float*)d_out;

    cudaFuncSetAttribute(gemm_merged,
        cudaFuncAttributeMaxDynamicSharedMemorySize, SMEM_GB);
    cudaFuncSetAttribute(gemm_proj,
        cudaFuncAttributeMaxDynamicSharedMemorySize, SMEM_GB);
    cudaFuncSetAttribute(attn_gemm,
        cudaFuncAttributeMaxDynamicSharedMemorySize, SMEM_GB);
    cudaFuncSetAttribute(kv2_mma,
        cudaFuncAttributeMaxDynamicSharedMemorySize, SMEM_KV2);
    cudaFuncSetAttribute(conv_s,
        cudaFuncAttributeMaxDynamicSharedMemorySize, 8 * 68 * 32 * 4);

    const int M = BATCH * SEQ;              // 32768
    const int XN4 = M * CH / 4;

    cudaStream_t side;
    cudaEvent_t evFork, evJoin;
    cudaStreamCreateWithFlags(&side, cudaStreamNonBlocking);
    cudaEventCreateWithFlags(&evFork, cudaEventDisableTiming);
    cudaEventCreateWithFlags(&evJoin, cudaEventDisableTiming);

    split_w<<<4 * CC / 1024, 256>>>(Wq, Wkv, Wproj);
    softplus_kernel<<<3, 256>>>(scale);
    split_x12<<<2 * (XN4 / 256), 256>>>(x1, x2, XN4);
    gemm_merged<<<dim3(15, M / BMM), 256, SMEM_GB>>>();        // v+k+q

    // fork: conv depends only on v splits; real room opens during 40-block kv2
    cudaEventRecord(evFork, 0);
    cudaStreamWaitEvent(side, evFork, 0);
    conv_s<<<dim3(BH, 16, 4), 256, 8 * 68 * 32 * 4, side>>>(dwc_w, dwc_b);
    cudaEventRecord(evJoin, side);

    qknorm_kernel<<<M / 8, 256>>>(pos);
    kv2_mma<<<BH, 256, SMEM_KV2>>>();            // 40 blocks, no atomics
    kv2t_split<<<dim3(BH, 64), 256>>>();

    cudaStreamWaitEvent(0, evJoin, 0);
    attn_gemm<<<BH * 32, 256, SMEM_GB>>>();

    gemm_proj<<<dim3(5, M / BMM), 256, SMEM_GB>>>(out, bproj);

    cudaEventDestroy(evFork);
    cudaEventDestroy(evJoin);
    cudaStreamDestroy(side);
}

// round 17
// speedup vs baseline: 1.0578x; 1.0578x over previous
#include <cuda_runtime.h>
#include <cuda_bf16.h>
#include <cstdint>
#include <cstddef>

// ---------------------------------------------------------------------------
// FocusedLinearAttention — round 17:
//   revert kv2 to 320-block atomic version (R16 regression);
//   gemm_core: peel g=0 and stagger the al LDM4s after g0's hi*hi MMAs.
// ---------------------------------------------------------------------------

#define BATCH 8
#define SEQ   4096
#define CH    640
#define CC    (CH*CH)
#define NH    5
#define HD    128
#define BH    (BATCH*NH)   // 40

#define BMM 128
#define BNN 128
#define BKE 32
#define NCHB (CH/BKE)           // 20
#define RWB 80
#define BUFB (128*RWB)
#define OFFAH 0
#define OFFAL BUFB
#define OFFBH (2*BUFB)
#define OFFBL (3*BUFB)
#define STB   (4*BUFB)          // 40960 B
#define SMEM_GB (2*STB)         // 81920 B -> 2 CTAs/SM

#define T2RW 272
#define T2BUF (32*T2RW)
#define OKH 0
#define OKL T2BUF
#define OVH (2*T2BUF)
#define OVL (3*T2BUF)
#define T2ST (4*T2BUF)          // 34816
#define SMEM_KV2 (2*T2ST)       // 69632

__device__ float g_q[BATCH*SEQ*CH];
__device__ float g_k[BATCH*SEQ*CH];
__device__ float g_x[BATCH*SEQ*CH];
__device__ __nv_bfloat16 g_abh[BATCH*SEQ*CH];
__device__ __nv_bfloat16 g_abl[BATCH*SEQ*CH];
__device__ __nv_bfloat16 g_a2h[BATCH*SEQ*CH];
__device__ __nv_bfloat16 g_a2l[BATCH*SEQ*CH];
__device__ __nv_bfloat16 g_qbh[BATCH*SEQ*CH];
__device__ __nv_bfloat16 g_qbl[BATCH*SEQ*CH];
__device__ __nv_bfloat16 g_kbh[BATCH*SEQ*CH];
__device__ __nv_bfloat16 g_kbl[BATCH*SEQ*CH];
__device__ __nv_bfloat16 g_vbh[BATCH*SEQ*CH];
__device__ __nv_bfloat16 g_vbl[BATCH*SEQ*CH];
__device__ __nv_bfloat16 g_wbh[4*CC];
__device__ __nv_bfloat16 g_wbl[4*CC];
__device__ __nv_bfloat16 g_k2h[BH*HD*HD];
__device__ __nv_bfloat16 g_k2l[BH*HD*HD];
__device__ float g_kv2[BH*HD*HD];
__device__ float g_ksum[BH*HD];
__device__ float g_sc[CH];

// ---------------------------------------------------------------------------
__device__ __forceinline__ void cp16(uint32_t dst, const void* src) {
    asm volatile("cp.async.cg.shared.global [%0], [%1], 16;" :: "r"(dst), "l"(src));
}

#define LDM4(r0, r1, r2, r3, a) \
    asm volatile("ldmatrix.sync.aligned.m8n8.x4.shared.b16 {%0,%1,%2,%3}, [%4];" \
        : "=r"(r0), "=r"(r1), "=r"(r2), "=r"(r3) : "r"(a))

#define LDM4T(r0, r1, r2, r3, a) \
    asm volatile("ldmatrix.sync.aligned.m8n8.x4.trans.shared.b16 {%0,%1,%2,%3}, [%4];" \
        : "=r"(r0), "=r"(r1), "=r"(r2), "=r"(r3) : "r"(a))

#define MMA_BF16(d, a, b) \
    asm volatile( \
        "mma.sync.aligned.m16n8k16.row.col.f32.bf16.bf16.f32 " \
        "{%0,%1,%2,%3}, {%4,%5,%6,%7}, {%8,%9}, {%0,%1,%2,%3};" \
        : "+f"((d)[0]), "+f"((d)[1]), "+f"((d)[2]), "+f"((d)[3]) \
        : "r"((a)[0]), "r"((a)[1]), "r"((a)[2]), "r"((a)[3]), \
          "r"((b)[0]), "r"((b)[1]))

// ---------------------------------------------------------------------------
__device__ __forceinline__ void split4(float4 v, __nv_bfloat16* hp, __nv_bfloat16* lp) {
    float f[4] = { v.x, v.y, v.z, v.w };
    __nv_bfloat16 h[4], l[4];
#pragma unroll
    for (int j = 0; j < 4; j++) {
        h[j] = __float2bfloat16_rn(f[j]);
        l[j] = __float2bfloat16_rn(f[j] - __bfloat162float(h[j]));
    }
    *reinterpret_cast<__nv_bfloat162*>(hp)     = { h[0], h[1] };
    *reinterpret_cast<__nv_bfloat162*>(hp + 2) = { h[2], h[3] };
    *reinterpret_cast<__nv_bfloat162*>(lp)     = { l[0], l[1] };
    *reinterpret_cast<__nv_bfloat162*>(lp + 2) = { l[2], l[3] };
}

// merged x1+x2 split
__global__ __launch_bounds__(256) void split_x12(
    const float* __restrict__ x1, const float* __restrict__ x2, int n4)
{
    int nb = gridDim.x >> 1;
    const float* src; __nv_bfloat16 *hi, *lo;
    int bi = blockIdx.x;
    if (bi < nb) { src = x1; hi = g_abh; lo = g_abl; }
    else         { src = x2; hi = g_a2h; lo = g_a2l; bi -= nb; }
    int i = bi * 256 + threadIdx.x;
    if (i >= n4) return;
    split4(reinterpret_cast<const float4*>(src)[i], hi + 4 * i, lo + 4 * i);
}

__global__ __launch_bounds__(256) void split_w(
    const float* __restrict__ Wq, const float* __restrict__ Wkv,
    const float* __restrict__ Wproj)
{
    int i = blockIdx.x * 256 + threadIdx.x;
    int fi = i * 4;
    const float* src; int off;
    if (fi < CC)          { src = Wq;    off = 0; }
    else if (fi < 3 * CC) { src = Wkv;   off = CC; }
    else                  { src = Wproj; off = 3 * CC; }
    float4 v = *reinterpret_cast<const float4*>(&src[fi - off]);
    split4(v, g_wbh + fi, g_wbl + fi);
}

// ---------------------------------------------------------------------------
// bf16x3 GEMM core (K = 640); single-sync mainloop; g=0 peeled, al staggered
// ---------------------------------------------------------------------------
__device__ __forceinline__ void gemm_core(
    const __nv_bfloat16* __restrict__ Ah, const __nv_bfloat16* __restrict__ Al,
    const __nv_bfloat16* __restrict__ Bh, const __nv_bfloat16* __restrict__ Bl,
    float* __restrict__ Cout, const float* __restrict__ bias,
    __nv_bfloat16* __restrict__ Hsp, __nv_bfloat16* __restrict__ Lsp,
    int m0, int nb0, int n0, uint32_t sb)
{
    const int tid = threadIdx.x;
    const int lane = tid & 31;
    const int wid = tid >> 5;
    const int warp_m = wid >> 1;
    const int warp_n = wid & 1;
    const int gid = lane >> 2;
    const int tig = lane & 3;
    const int lr = (lane & 7) + ((lane >> 3) & 1) * 8;
    const uint32_t lc = (uint32_t)(((lane >> 4) & 1) * 16);

    float acc[2][8][4];
#pragma unroll
    for (int t = 0; t < 2; t++)
#pragma unroll
        for (int j = 0; j < 8; j++)
#pragma unroll
            for (int e = 0; e < 4; e++) acc[t][j][e] = 0.f;

    int r0f = tid >> 2, c0f = tid & 3;
    int r1f = (tid + 256) >> 2, c1f = (tid + 256) & 3;
    const uint32_t so0 = (uint32_t)(r0f * RWB + c0f * 16);
    const uint32_t so1 = (uint32_t)(r1f * RWB + c1f * 16);
    const size_t gA0 = (size_t)(m0 + r0f) * CH + c0f * 8;
    const size_t gA1 = (size_t)(m0 + r1f) * CH + c1f * 8;
    const size_t gB0 = (size_t)(nb0 + r0f) * CH + c0f * 8;
    const size_t gB1 = (size_t)(nb0 + r1f) * CH + c1f * 8;

    auto fill = [&](int stage, int chunk) {
        const int k0 = chunk * BKE;
        const uint32_t stb = sb + (uint32_t)(stage * STB);
        cp16(stb + OFFAH + so0, Ah + gA0 + k0);
        cp16(stb + OFFAL + so0, Al + gA0 + k0);
        cp16(stb + OFFBH + so0, Bh + gB0 + k0);
        cp16(stb + OFFBL + so0, Bl + gB0 + k0);
        cp16(stb + OFFAH + so1, Ah + gA1 + k0);
        cp16(stb + OFFAL + so1, Al + gA1 + k0);
        cp16(stb + OFFBH + so1, Bh + gB1 + k0);
        cp16(stb + OFFBL + so1, Bl + gB1 + k0);
        asm volatile("cp.async.commit_group;" ::: "memory");
    };

    const uint32_t raF = (uint32_t)((warp_m * 32 + lr) * RWB) + lc;
    const uint32_t rbF = (uint32_t)((warp_n * 64 + lr) * RWB) + lc;

    fill(0, 0);
    for (int i = 0; i < NCHB; i++) {
        asm volatile("cp.async.wait_group 0;" ::: "memory");
        __syncthreads();
        if (i + 1 < NCHB) fill((i + 1) & 1, i + 1);

        const uint32_t stb = sb + (uint32_t)((i & 1) * STB);
#pragma unroll
        for (int ks = 0; ks < 2; ks++) {
            const uint32_t kofs = (uint32_t)(ks * 32);
            uint32_t ah[2][4], al[2][4];
            uint32_t ra0 = stb + OFFAH + raF + kofs;
            uint32_t ra1 = ra0 + (uint32_t)(16 * RWB);
            LDM4(ah[0][0], ah[0][1], ah[0][2], ah[0][3], ra0);
            LDM4(ah[1][0], ah[1][1], ah[1][2], ah[1][3], ra1);

            // ---- g = 0 peeled: hi*hi first, al LDM4s staggered after ----
            {
                uint32_t rb = stb + OFFBH + rbF + kofs;
                uint32_t bh4[4], bl4[4];
                LDM4(bh4[0], bh4[1], bh4[2], bh4[3], rb);
                uint32_t b0h[2] = { bh4[0], bh4[2] }, b1h[2] = { bh4[1], bh4[3] };
#pragma unroll
                for (int t = 0; t < 2; t++) {
                    MMA_BF16(acc[t][0], ah[t], b0h);
                    MMA_BF16(acc[t][1], ah[t], b1h);
                }
                LDM4(al[0][0], al[0][1], al[0][2], al[0][3], ra0 + (OFFAL - OFFAH));
                LDM4(al[1][0], al[1][1], al[1][2], al[1][3], ra1 + (OFFAL - OFFAH));
                LDM4(bl4[0], bl4[1], bl4[2], bl4[3], rb + (OFFBL - OFFBH));
                uint32_t b0l[2] = { bl4[0], bl4[2] }, b1l[2] = { bl4[1], bl4[3] };
#pragma unroll
                for (int t = 0; t < 2; t++) {
                    MMA_BF16(acc[t][0], al[t], b0h);
                    MMA_BF16(acc[t][1], al[t], b1h);
                }
#pragma unroll
                for (int t = 0; t < 2; t++) {
                    MMA_BF16(acc[t][0], ah[t], b0l);
                    MMA_BF16(acc[t][1], ah[t], b1l);
                }
            }
            // ---- g = 1..3 ----
#pragma unroll
            for (int g = 1; g < 4; g++) {
                uint32_t rb = stb + OFFBH + rbF + (uint32_t)(g * 16 * RWB) + kofs;
                uint32_t bh4[4], bl4[4];
                LDM4(bh4[0], bh4[1], bh4[2], bh4[3], rb);
                uint32_t b0h[2] = { bh4[0], bh4[2] }, b1h[2] = { bh4[1], bh4[3] };
#pragma unroll
                for (int t = 0; t < 2; t++) {
                    MMA_BF16(acc[t][2*g],   ah[t], b0h);
                    MMA_BF16(acc[t][2*g+1], ah[t], b1h);
                }
                LDM4(bl4[0], bl4[1], bl4[2], bl4[3], rb + (OFFBL - OFFBH));
                uint32_t b0l[2] = { bl4[0], bl4[2] }, b1l[2] = { bl4[1], bl4[3] };
#pragma unroll
                for (int t = 0; t < 2; t++) {
                    MMA_BF16(acc[t][2*g],   al[t], b0h);
                    MMA_BF16(acc[t][2*g+1], al[t], b1h);
                }
#pragma unroll
                for (int t = 0; t < 2; t++) {
                    MMA_BF16(acc[t][2*g],   ah[t], b0l);
                    MMA_BF16(acc[t][2*g+1], ah[t], b1l);
                }
            }
        }
    }

#pragma unroll
    for (int t = 0; t < 2; t++) {
        int r0 = m0 + warp_m * 32 + t * 16 + gid;
#pragma unroll
        for (int j = 0; j < 8; j++) {
            int cc = n0 + warp_n * 64 + j * 8 + 2 * tig;
            float b0 = bias ? bias[cc] : 0.f;
            float b1 = bias ? bias[cc + 1] : 0.f;
            float f00 = acc[t][j][0] + b0, f01 = acc[t][j][1] + b1;
            float f10 = acc[t][j][2] + b0, f11 = acc[t][j][3] + b1;
            if (Cout) {
                *reinterpret_cast<float2*>(&Cout[(size_t)r0 * CH + cc]) =
                    make_float2(f00, f01);
                *reinterpret_cast<float2*>(&Cout[(size_t)(r0 + 8) * CH + cc]) =
                    make_float2(f10, f11);
            }
            if (Hsp) {
                __nv_bfloat16 h0 = __float2bfloat16_rn(f00);
                __nv_bfloat16 h1 = __float2bfloat16_rn(f01);
                __nv_bfloat16 h2 = __float2bfloat16_rn(f10);
                __nv_bfloat16 h3 = __float2bfloat16_rn(f11);
                __nv_bfloat16 l0 = __float2bfloat16_rn(f00 - __bfloat162float(h0));
                __nv_bfloat16 l1 = __float2bfloat16_rn(f01 - __bfloat162float(h1));
                __nv_bfloat16 l2 = __float2bfloat16_rn(f10 - __bfloat162float(h2));
                __nv_bfloat16 l3 = __float2bfloat16_rn(f11 - __bfloat162float(h3));
                *reinterpret_cast<__nv_bfloat162*>(&Hsp[(size_t)r0 * CH + cc]) = { h0, h1 };
                *reinterpret_cast<__nv_bfloat162*>(&Hsp[(size_t)(r0 + 8) * CH + cc]) = { h2, h3 };
                *reinterpret_cast<__nv_bfloat162*>(&Lsp[(size_t)r0 * CH + cc]) = { l0, l1 };
                *reinterpret_cast<__nv_bfloat162*>(&Lsp[(size_t)(r0 + 8) * CH + cc]) = { l2, l3 };
            }
        }
    }
}

// merged v + kq GEMM: grid (15, 256); v -> split-only output
__global__ __launch_bounds__(256, 2) void gemm_merged() {
    extern __shared__ char smem[];
    const uint32_t sb = (uint32_t)__cvta_generic_to_shared(smem);
    const int m0 = blockIdx.y * BMM;
    const int bx = blockIdx.x;
    if (bx < 5) {
        gemm_core(g_a2h, g_a2l, g_wbh, g_wbl, nullptr, nullptr,
                  g_vbh, g_vbl, m0, bx * BNN, bx * BNN, sb);
    } else {
        int nb0 = (bx - 5) * BNN;
        if (nb0 < CH)
            gemm_core(g_abh, g_abl, g_wbh + CC, g_wbl + CC, g_k, nullptr,
                      nullptr, nullptr, m0, nb0, nb0, sb);
        else
            gemm_core(g_abh, g_abl, g_wbh + CC, g_wbl + CC, g_q, nullptr,
                      nullptr, nullptr, m0, nb0, nb0 - CH, sb);
    }
}

// proj GEMM: grid (5, 256)
__global__ __launch_bounds__(256, 2) void gemm_proj(
    float* __restrict__ out, const float* __restrict__ bias)
{
    extern __shared__ char smem[];
    const uint32_t sb = (uint32_t)__cvta_generic_to_shared(smem);
    gemm_core(g_abh, g_abl, g_wbh + 3 * CC, g_wbl + 3 * CC, out, bias,
              nullptr, nullptr,
              blockIdx.y * BMM, blockIdx.x * BNN, blockIdx.x * BNN, sb);
}

// ---------------------------------------------------------------------------
// kv2 on tensor pipe: grid (BH, 8) with atomics (320 blocks) + fused ksum
// ---------------------------------------------------------------------------
__global__ __launch_bounds__(256, 2) void kv2_mma() {
    extern __shared__ char smem[];
    const uint32_t sb = (uint32_t)__cvta_generic_to_shared(smem);
    const int bh = blockIdx.x, jc = blockIdx.y;
    const int b = bh / NH, hoff = (bh % NH) * HD;
    const __nv_bfloat16* Kh = g_kbh + (size_t)b * SEQ * CH + hoff;
    const __nv_bfloat16* Kl = g_kbl + (size_t)b * SEQ * CH + hoff;
    const __nv_bfloat16* Vh = g_vbh + (size_t)b * SEQ * CH + hoff;
    const __nv_bfloat16* Vl = g_vbl + (size_t)b * SEQ * CH + hoff;

    const int tid = threadIdx.x;
    const int lane = tid & 31;
    const int wid = tid >> 5;
    const int warp_m = wid >> 1;
    const int warp_n = wid & 1;
    const int gid = lane >> 2;
    const int tig = lane & 3;
    const int grp = lane >> 3;
    const int l8 = lane & 7;

    float acc[2][8][4];
#pragma unroll
    for (int t = 0; t < 2; t++)
#pragma unroll
        for (int j = 0; j < 8; j++)
#pragma unroll
            for (int e = 0; e < 4; e++) acc[t][j][e] = 0.f;

    float kacc = 0.f;

    auto fill = [&](int stage, int it) {
        const int j0 = jc * 512 + it * 32;
        const uint32_t stb = sb + (uint32_t)(stage * T2ST);
#pragma unroll
        for (int t = 0; t < 2; t++) {
            int u = tid + t * 256;
            int row = u >> 4, col = u & 15;
            uint32_t off = (uint32_t)(row * T2RW + col * 16);
            size_t g = (size_t)(j0 + row) * CH + col * 8;
            cp16(stb + OKH + off, Kh + g);
            cp16(stb + OKL + off, Kl + g);
            cp16(stb + OVH + off, Vh + g);
            cp16(stb + OVL + off, Vl + g);
        }
        asm volatile("cp.async.commit_group;" ::: "memory");
    };

    fill(0, 0);
    for (int it = 0; it < 16; it++) {
        asm volatile("cp.async.wait_group 0;" ::: "memory");
        __syncthreads();
        if (it + 1 < 16) fill((it + 1) & 1, it + 1);

        const uint32_t stb = sb + (uint32_t)((it & 1) * T2ST);

        if (tid < 128) {
            const __nv_bfloat16* KhS = reinterpret_cast<const __nv_bfloat16*>(
                smem + (it & 1) * T2ST + OKH);
            const __nv_bfloat16* KlS = reinterpret_cast<const __nv_bfloat16*>(
                smem + (it & 1) * T2ST + OKL);
#pragma unroll
            for (int j = 0; j < 32; j++)
                kacc += __bfloat162float(KhS[j * (T2RW / 2) + tid]) +
                        __bfloat162float(KlS[j * (T2RW / 2) + tid]);
        }

#pragma unroll
        for (int ks = 0; ks < 2; ks++) {
            const uint32_t aj = (uint32_t)(ks * 16 + ((grp >> 1) & 1) * 8 + l8);
            uint32_t ah[2][4], al[2][4];
#pragma unroll
            for (int t = 0; t < 2; t++) {
                uint32_t ac = (uint32_t)(warp_m * 32 + t * 16 + (grp & 1) * 8);
                uint32_t ra = stb + OKH + aj * T2RW + ac * 2;
                LDM4T(ah[t][0], ah[t][1], ah[t][2], ah[t][3], ra);
                LDM4T(al[t][0], al[t][1], al[t][2], al[t][3], ra + (OKL - OKH));
            }
            const uint32_t bj = (uint32_t)(ks * 16 + (grp & 1) * 8 + l8);
#pragma unroll
            for (int g = 0; g < 4; g++) {
                uint32_t bd = (uint32_t)(warp_n * 64 + g * 16 + ((grp >> 1) & 1) * 8);
                uint32_t rb = stb + OVH + bj * T2RW + bd * 2;
                uint32_t bh4[4], bl4[4];
                LDM4T(bh4[0], bh4[1], bh4[2], bh4[3], rb);
                uint32_t b0h[2] = { bh4[0], bh4[1] }, b1h[2] = { bh4[2], bh4[3] };
#pragma unroll
                for (int t = 0; t < 2; t++) {
                    MMA_BF16(acc[t][2*g],   ah[t], b0h);
                    MMA_BF16(acc[t][2*g+1], ah[t], b1h);
                }
                LDM4T(bl4[0], bl4[1], bl4[2], bl4[3], rb + (OVL - OVH));
                uint32_t b0l[2] = { bl4[0], bl4[1] }, b1l[2] = { bl4[2], bl4[3] };
#pragma unroll
                for (int t = 0; t < 2; t++) {
                    MMA_BF16(acc[t][2*g],   al[t], b0h);
                    MMA_BF16(acc[t][2*g+1], al[t], b1h);
                }
#pragma unroll
                for (int t = 0; t < 2; t++) {
                    MMA_BF16(acc[t][2*g],   ah[t], b0l);
                    MMA_BF16(acc[t][2*g+1], ah[t], b1l);
                }
            }
        }
    }

    if (tid < 128) atomicAdd(&g_ksum[bh * HD + tid], kacc);

    float* dst = g_kv2 + bh * HD * HD;
#pragma unroll
    for (int t = 0; t < 2; t++) {
        int c0 = warp_m * 32 + t * 16 + gid;
#pragma unroll
        for (int j = 0; j < 8; j++) {
            int d = warp_n * 64 + j * 8 + 2 * tig;
            atomicAdd(&dst[c0 * HD + d],           acc[t][j][0]);
            atomicAdd(&dst[c0 * HD + d + 1],       acc[t][j][1]);
            atomicAdd(&dst[(c0 + 8) * HD + d],     acc[t][j][2]);
            atomicAdd(&dst[(c0 + 8) * HD + d + 1], acc[t][j][3]);
        }
    }
}

// ---------------------------------------------------------------------------
// attn GEMM with fused z (K=128, 4 chunks); single-sync loop
// ---------------------------------------------------------------------------
__global__ __launch_bounds__(256, 2) void attn_gemm() {
    extern __shared__ char smem[];
    const uint32_t sb = (uint32_t)__cvta_generic_to_shared(smem);
    const int bx = blockIdx.x;
    const int bh = bx >> 5;
    const int m0 = (bx & 31) * BMM;
    const int b = bh / NH, hoff = (bh % NH) * HD;
    const __nv_bfloat16* Ah = g_qbh + (size_t)b * SEQ * CH + hoff;
    const __nv_bfloat16* Al = g_qbl + (size_t)b * SEQ * CH + hoff;
    const __nv_bfloat16* Bh = g_k2h + (size_t)bh * HD * HD;
    const __nv_bfloat16* Bl = g_k2l + (size_t)bh * HD * HD;

    const int tid = threadIdx.x;
    const int lane = tid & 31;
    const int wid = tid >> 5;
    const int warp_m = wid >> 1;
    const int warp_n = wid & 1;
    const int gid = lane >> 2;
    const int tig = lane & 3;
    const int lr = (lane & 7) + ((lane >> 3) & 1) * 8;
    const uint32_t lc = (uint32_t)(((lane >> 4) & 1) * 16);

    float acc[2][8][4];
#pragma unroll
    for (int t = 0; t < 2; t++)
#pragma unroll
        for (int j = 0; j < 8; j++)
#pragma unroll
            for (int e = 0; e < 4; e++) acc[t][j][e] = 0.f;

    int r0f = tid >> 2, c0f = tid & 3;
    int r1f = (tid + 256) >> 2, c1f = (tid + 256) & 3;
    const uint32_t so0 = (uint32_t)(r0f * RWB + c0f * 16);
    const uint32_t so1 = (uint32_t)(r1f * RWB + c1f * 16);
    const size_t gA0 = (size_t)(m0 + r0f) * CH + c0f * 8;
    const size_t gA1 = (size_t)(m0 + r1f) * CH + c1f * 8;
    const size_t gB0 = (size_t)r0f * HD + c0f * 8;
    const size_t gB1 = (size_t)r1f * HD + c1f * 8;

    auto fill = [&](int stage, int chunk) {
        const int k0 = chunk * BKE;
        const uint32_t stb = sb + (uint32_t)(stage * STB);
        cp16(stb + OFFAH + so0, Ah + gA0 + k0);
        cp16(stb + OFFAL + so0, Al + gA0 + k0);
        cp16(stb + OFFBH + so0, Bh + gB0 + k0);
        cp16(stb + OFFBL + so0, Bl + gB0 + k0);
        cp16(stb + OFFAH + so1, Ah + gA1 + k0);
        cp16(stb + OFFAL + so1, Al + gA1 + k0);
        cp16(stb + OFFBH + so1, Bh + gB1 + k0);
        cp16(stb + OFFBL + so1, Bl + gB1 + k0);
        asm volatile("cp.async.commit_group;" ::: "memory");
    };

    const uint32_t raF = (uint32_t)((warp_m * 32 + lr) * RWB) + lc;
    const uint32_t rbF = (uint32_t)((warp_n * 64 + lr) * RWB) + lc;

    float zacc = 0.f;

    fill(0, 0);
#pragma unroll
    for (int i = 0; i < 4; i++) {
        asm volatile("cp.async.wait_group 0;" ::: "memory");
        __syncthreads();
        if (i + 1 < 4) fill((i + 1) & 1, i + 1);

        const uint32_t stb = sb + (uint32_t)((i & 1) * STB);

        if (tid < 128) {
            const uint32_t qh = stb + OFFAH + (uint32_t)(tid * RWB);
            const float* ksp = g_ksum + bh * HD + i * BKE;
#pragma unroll
            for (int cc = 0; cc < 32; cc += 2) {
                uint32_t hv, lv;
                asm("ld.shared.b32 %0, [%1];" : "=r"(hv) : "r"(qh + cc * 2));
                asm("ld.shared.b32 %0, [%1];" : "=r"(lv)
                    : "r"(qh + (OFFAL - OFFAH) + cc * 2));
                __nv_bfloat162 h2 = *reinterpret_cast<__nv_bfloat162*>(&hv);
                __nv_bfloat162 l2 = *reinterpret_cast<__nv_bfloat162*>(&lv);
                float q0 = __bfloat162float(h2.x) + __bfloat162float(l2.x);
                float q1 = __bfloat162float(h2.y) + __bfloat162float(l2.y);
                zacc += q0 * __ldg(ksp + cc) + q1 * __ldg(ksp + cc + 1);
            }
        }

#pragma unroll
        for (int ks = 0; ks < 2; ks++) {
            const uint32_t kofs = (uint32_t)(ks * 32);
            uint32_t ah[2][4], al[2][4];
#pragma unroll
            for (int t = 0; t < 2; t++) {
                uint32_t ra = stb + OFFAH + raF + (uint32_t)(t * 16 * RWB) + kofs;
                LDM4(ah[t][0], ah[t][1], ah[t][2], ah[t][3], ra);
                LDM4(al[t][0], al[t][1], al[t][2], al[t][3], ra + (OFFAL - OFFAH));
            }
#pragma unroll
            for (int g = 0; g < 4; g++) {
                uint32_t rb = stb + OFFBH + rbF + (uint32_t)(g * 16 * RWB) + kofs;
                uint32_t bh4[4], bl4[4];
                LDM4(bh4[0], bh4[1], bh4[2], bh4[3], rb);
                uint32_t b0h[2] = { bh4[0], bh4[2] }, b1h[2] = { bh4[1], bh4[3] };
#pragma unroll
                for (int t = 0; t < 2; t++) {
                    MMA_BF16(acc[t][2*g],   ah[t], b0h);
                    MMA_BF16(acc[t][2*g+1], ah[t], b1h);
                }
                LDM4(bl4[0], bl4[1], bl4[2], bl4[3], rb + (OFFBL - OFFBH));
                uint32_t b0l[2] = { bl4[0], bl4[2] }, b1l[2] = { bl4[1], bl4[3] };
#pragma unroll
                for (int t = 0; t < 2; t++) {
                    MMA_BF16(acc[t][2*g],   al[t], b0h);
                    MMA_BF16(acc[t][2*g+1], al[t], b1h);
                }
#pragma unroll
                for (int t = 0; t < 2; t++) {
                    MMA_BF16(acc[t][2*g],   ah[t], b0l);
                    MMA_BF16(acc[t][2*g+1], ah[t], b1l);
                }
            }
        }
    }

    __syncthreads();
    float* zs = reinterpret_cast<float*>(smem);
    if (tid < 128) zs[tid] = 1.f / (zacc + 1e-6f);
    __syncthreads();

#pragma unroll
    for (int t = 0; t < 2; t++) {
        int lr0 = warp_m * 32 + t * 16 + gid;
#pragma unroll
        for (int j = 0; j < 8; j++) {
            int d = warp_n * 64 + j * 8 + 2 * tig;
#pragma unroll
            for (int half = 0; half < 2; half++) {
                int lrow = lr0 + half * 8;
                int i = m0 + lrow;
                float zv = zs[lrow];
                size_t base = (size_t)(b * SEQ + i) * CH + hoff + d;
                float f0 = g_x[base]     + acc[t][j][half * 2]     * zv;
                float f1 = g_x[base + 1] + acc[t][j][half * 2 + 1] * zv;
                __nv_bfloat16 h0 = __float2bfloat16_rn(f0);
                __nv_bfloat16 h1 = __float2bfloat16_rn(f1);
                __nv_bfloat16 l0 = __float2bfloat16_rn(f0 - __bfloat162float(h0));
                __nv_bfloat16 l1 = __float2bfloat16_rn(f1 - __bfloat162float(h1));
                *reinterpret_cast<__nv_bfloat162*>(&g_abh[base]) = { h0, h1 };
                *reinterpret_cast<__nv_bfloat162*>(&g_abl[base]) = { l0, l1 };
            }
        }
    }
}

// ---------------------------------------------------------------------------
__global__ void softplus_kernel(const float* __restrict__ scale) {
    int c = blockIdx.x * 256 + threadIdx.x;
    if (c < CH) g_sc[c] = log1pf(expf(scale[c]));
}

// ---------------------------------------------------------------------------
__device__ __forceinline__ float warp_sum(float s) {
#pragma unroll
    for (int o = 16; o > 0; o >>= 1) s += __shfl_xor_sync(0xffffffffu, s, o);
    return s;
}

// qknorm: warp per row; q and k both -> bf16 hi/lo.
__global__ __launch_bounds__(256) void qknorm_kernel(const float* __restrict__ pos) {
    const int w = blockIdx.x * 8 + (threadIdx.x >> 5);
    const int lane = threadIdx.x & 31;
    const size_t row = (size_t)w;
    const int n = w & (SEQ - 1);
    const float* qrow = g_q + row * CH;
    const float* krow = g_k + row * CH;
    const float* prow = pos + (size_t)n * CH;

    float scv[20];
#pragma unroll
    for (int t = 0; t < 20; t++) scv[t] = g_sc[lane + 32 * t];

    {
        float v[20]; float s = 0.f;
#pragma unroll
        for (int t = 0; t < 20; t++) {
            float raw = qrow[lane + 32 * t];
            float val = (fmaxf(raw, 0.f) + 1e-6f) / scv[t];
            v[t] = val; s += val * val;
        }
        float n1 = sqrtf(warp_sum(s));
        s = 0.f;
#pragma unroll
        for (int t = 0; t < 20; t++) { float c3 = v[t]*v[t]*v[t]; v[t] = c3; s += c3*c3; }
        float sc2 = n1 / sqrtf(warp_sum(s));
#pragma unroll
        for (int t = 0; t < 20; t++) {
            float f = v[t] * sc2;
            __nv_bfloat16 h = __float2bfloat16_rn(f);
            __nv_bfloat16 l = __float2bfloat16_rn(f - __bfloat162float(h));
            g_qbh[row * CH + lane + 32 * t] = h;
            g_qbl[row * CH + lane + 32 * t] = l;
        }
    }
    {
        float v[20]; float s = 0.f;
#pragma unroll
        for (int t = 0; t < 20; t++) {
            float raw = krow[lane + 32 * t] + prow[lane + 32 * t];
            float val = (fmaxf(raw, 0.f) + 1e-6f) / scv[t];
            v[t] = val; s += val * val;
        }
        float n1 = sqrtf(warp_sum(s));
        s = 0.f;
#pragma unroll
        for (int t = 0; t < 20; t++) { float c3 = v[t]*v[t]*v[t]; v[t] = c3; s += c3*c3; }
        float sc2 = n1 / sqrtf(warp_sum(s));
#pragma unroll
        for (int t = 0; t < 20; t++) {
            float f = v[t] * sc2;
            __nv_bfloat16 h = __float2bfloat16_rn(f);
            __nv_bfloat16 l = __float2bfloat16_rn(f - __bfloat162float(h));
            g_kbh[row * CH + lane + 32 * t] = h;
            g_kbl[row * CH + lane + 32 * t] = l;
        }
    }
}

__global__ void zero_kernel() {
    int idx = blockIdx.x * 256 + threadIdx.x;
    if (idx < BH * HD * HD) g_kv2[idx] = 0.f;
    if (idx < BH * HD)      g_ksum[idx] = 0.f;
}

// kv2^T + bf16 split: [bh][c][d] fp32 -> [bh][d][c] hi/lo
__global__ __launch_bounds__(256) void kv2t_split() {
    const int bh = blockIdx.x;
    const int e = blockIdx.y * 256 + threadIdx.x;
    const int d = e >> 7, c = e & 127;
    float v = g_kv2[bh * HD * HD + c * HD + d];
    __nv_bfloat16 h = __float2bfloat16_rn(v);
    __nv_bfloat16 l = __float2bfloat16_rn(v - __bfloat162float(h));
    g_k2h[bh * HD * HD + d * HD + c] = h;
    g_k2l[bh * HD * HD + d * HD + c] = l;
}

// ---------------------------------------------------------------------------
// depthwise conv reading v hi/lo splits
// ---------------------------------------------------------------------------
__global__ __launch_bounds__(256) void conv_s(
    const float* __restrict__ w, const float* __restrict__ bias)
{
    extern __shared__ float sv[];   // [8][68][32]
    const int bh = blockIdx.x, yt = blockIdx.y, dc = blockIdx.z;
    const int b = bh / NH, hoff = (bh % NH) * HD;
    const int tid = threadIdx.x;
    const int d = tid & 31;
    const int xg = tid >> 5;
    const __nv_bfloat16* vh = g_vbh + (size_t)b * SEQ * CH + hoff + dc * 32;
    const __nv_bfloat16* vl = g_vbl + (size_t)b * SEQ * CH + hoff + dc * 32;

    {
        int p = tid;
        int r = p >> 5, rest = p & 31;
        int xi = rest >> 3, d4 = rest & 7;
        int ix = (xi < 2) ? xi : (xi + 64);
        *reinterpret_cast<float4*>(&sv[(r * 68 + ix) * 32 + d4 * 4]) =
            make_float4(0.f, 0.f, 0.f, 0.f);
    }
    for (int p = tid; p < 2048; p += 256) {
        int r = p >> 8, rest = p & 255;
        int x = rest >> 2, d8 = rest & 3;
        int y = yt * 4 - 2 + r;
        float f[8];
        if ((unsigned)y < 64u) {
            uint4 hv = *reinterpret_cast<const uint4*>(
                &vh[(size_t)(y * 64 + x) * CH + d8 * 8]);
            uint4 lv = *reinterpret_cast<const uint4*>(
                &vl[(size_t)(y * 64 + x) * CH + d8 * 8]);
            const __nv_bfloat162* h2 = reinterpret_cast<const __nv_bfloat162*>(&hv);
            const __nv_bfloat162* l2 = reinterpret_cast<const __nv_bfloat162*>(&lv);
#pragma unroll
            for (int j = 0; j < 4; j++) {
                f[2*j]   = __bfloat162float(h2[j].x) + __bfloat162float(l2[j].x);
                f[2*j+1] = __bfloat162float(h2[j].y) + __bfloat162float(l2[j].y);
            }
        } else {
#pragma unroll
            for (int j = 0; j < 8; j++) f[j] = 0.f;
        }
        float* dst = &sv[(r * 68 + x + 2) * 32 + d8 * 8];
        *reinterpret_cast<float4*>(dst)     = make_float4(f[0], f[1], f[2], f[3]);
        *reinterpret_cast<float4*>(dst + 4) = make_float4(f[4], f[5], f[6], f[7]);
    }
    __syncthreads();

    float wr[25];
#pragma unroll
    for (int k = 0; k < 25; k++) wr[k] = __ldg(&w[(dc * 32 + d) * 25 + k]);
    const float bv = __ldg(&bias[dc * 32 + d]);

#pragma unroll
    for (int y = 0; y < 4; y++) {
#pragma unroll
        for (int xo = 0; xo < 8; xo++) {
            int x = xg * 8 + xo;
            float acc = bv;
#pragma unroll
            for (int ky = 0; ky < 5; ky++)
#pragma unroll
                for (int kx = 0; kx < 5; kx++)
                    acc += wr[ky * 5 + kx] * sv[((y + ky) * 68 + (x + kx)) * 32 + d];
            int oy = yt * 4 + y;
            g_x[(size_t)(b * SEQ + oy * 64 + x) * CH + hoff + dc * 32 + d] = acc;
        }
    }
}

// ---------------------------------------------------------------------------
extern "C" void kernel_launch(void* const* d_in, const int* in_sizes, int n_in,
                              void* d_out, int out_size)
{
    const float* x1    = (const float*)d_in[0];
    const float* x2    = (const float*)d_in[1];
    const float* Wq    = (const float*)d_in[2];
    const float* Wkv   = (const float*)d_in[3];
    const float* Wproj = (const float*)d_in[4];
    const float* bproj = (const float*)d_in[5];
    const float* dwc_w = (const float*)d_in[6];
    const float* dwc_b = (const float*)d_in[7];
    const float* scale = (const float*)d_in[8];
    const float* pos   = (const float*)d_in[9];
    float* out = (float*)d_out;

    cudaFuncSetAttribute(gemm_merged,
        cudaFuncAttributeMaxDynamicSharedMemorySize, SMEM_GB);
    cudaFuncSetAttribute(gemm_proj,
        cudaFuncAttributeMaxDynamicSharedMemorySize, SMEM_GB);
    cudaFuncSetAttribute(attn_gemm,
        cudaFuncAttributeMaxDynamicSharedMemorySize, SMEM_GB);
    cudaFuncSetAttribute(kv2_mma,
        cudaFuncAttributeMaxDynamicSharedMemorySize, SMEM_KV2);
    cudaFuncSetAttribute(conv_s,
        cudaFuncAttributeMaxDynamicSharedMemorySize, 8 * 68 * 32 * 4);

    const int M = BATCH * SEQ;              // 32768
    const int XN4 = M * CH / 4;

    cudaStream_t side;
    cudaEvent_t evFork, evJoin;
    cudaStreamCreateWithFlags(&side, cudaStreamNonBlocking);
    cudaEventCreateWithFlags(&evFork, cudaEventDisableTiming);
    cudaEventCreateWithFlags(&evJoin, cudaEventDisableTiming);

    split_w<<<4 * CC / 1024, 256>>>(Wq, Wkv, Wproj);
    softplus_kernel<<<3, 256>>>(scale);
    zero_kernel<<<(BH * HD * HD + 255) / 256, 256>>>();
    split_x12<<<2 * (XN4 / 256), 256>>>(x1, x2, XN4);
    gemm_merged<<<dim3(15, M / BMM), 256, SMEM_GB>>>();        // v+k+q

    // fork: conv depends only on v splits
    cudaEventRecord(evFork, 0);
    cudaStreamWaitEvent(side, evFork, 0);
    conv_s<<<dim3(BH, 16, 4), 256, 8 * 68 * 32 * 4, side>>>(dwc_w, dwc_b);
    cudaEventRecord(evJoin, side);

    qknorm_kernel<<<M / 8, 256>>>(pos);
    kv2_mma<<<dim3(BH, 8), 256, SMEM_KV2>>>();   // 320 blocks + atomics
    kv2t_split<<<dim3(BH, 64), 256>>>();

    cudaStreamWaitEvent(0, evJoin, 0);
    attn_gemm<<<BH * 32, 256, SMEM_GB>>>();

    gemm_proj<<<dim3(5, M / BMM), 256, SMEM_GB>>>(out, bproj);

    cudaEventDestroy(evFork);
    cudaEventDestroy(evJoin);
    cudaStreamDestroy(side);
}